// round 14
// baseline (speedup 1.0000x reference)
#include <cuda_runtime.h>
#include <cuda_bf16.h>
#include <cstdint>

#define B_    16
#define NSEQ  1168
#define H_    8
#define DH    32
#define C_    256
#define NPAD  1280
#define MROWS (B_*NSEQ)   // 18688 = 146*128
#define LOG2E 1.4426950408889634f
#define QK_SCALE (0.1767766952966369f * LOG2E)   // 32^-0.5 * log2(e), folded into q

// ---------------- scratch (device globals; no runtime alloc) ----------------
__device__ __align__(16) __nv_bfloat16  g_q[(size_t)B_ * H_ * NSEQ * DH];
__device__ __align__(16) __nv_bfloat16  g_k[(size_t)B_ * H_ * NSEQ * DH];
__device__ __align__(16) __nv_bfloat16  g_v[(size_t)B_ * H_ * NSEQ * DH];
__device__ __align__(16) __nv_bfloat16  g_bias[(size_t)H_ * NSEQ * NPAD];  // frag-ordered, *log2e
__device__ __align__(16) float g_att[(size_t)MROWS * C_];     // tf32-rounded by attn epilogue
__device__ __align__(16) float g_madd[(size_t)B_ * NPAD];     // frag-ordered additive mask
__device__ __align__(16) float g_wq[768 * 256];               // tf32-rounded, k-permuted w_qkv
__device__ __align__(16) float g_wp[256 * 256];               // tf32-rounded, k-permuted w_proj

// ---------------- helpers ----------------
__device__ __forceinline__ float tf32r(float x) {
    uint32_t u;
    asm("cvt.rna.tf32.f32 %0, %1;" : "=r"(u) : "f"(x));
    return __uint_as_float(u);
}
__device__ __forceinline__ float ex2f(float x) {
    float y;
    asm("ex2.approx.ftz.f32 %0, %1;" : "=f"(y) : "f"(x));
    return y;
}
__device__ __forceinline__ uint32_t pack_bf16(float x, float y) {
    __nv_bfloat162 h = __floats2bfloat162_rn(x, y);
    return *reinterpret_cast<uint32_t*>(&h);
}
__device__ __forceinline__ float2 unpack_bf16(uint32_t u) {
    __nv_bfloat162 h = *reinterpret_cast<__nv_bfloat162*>(&u);
    return __bfloat1622float2(h);
}
__device__ __forceinline__ uint32_t u4w(const uint4& v, int w) {
    return w == 0 ? v.x : w == 1 ? v.y : w == 2 ? v.z : v.w;
}
__device__ __forceinline__ void mma_tf32(float& d0, float& d1, float& d2, float& d3,
                                         uint32_t a0, uint32_t a1, uint32_t a2, uint32_t a3,
                                         uint32_t b0, uint32_t b1) {
    asm volatile("mma.sync.aligned.m16n8k8.row.col.f32.tf32.tf32.f32 "
                 "{%0,%1,%2,%3},{%4,%5,%6,%7},{%8,%9},{%0,%1,%2,%3};"
                 : "+f"(d0), "+f"(d1), "+f"(d2), "+f"(d3)
                 : "r"(a0), "r"(a1), "r"(a2), "r"(a3), "r"(b0), "r"(b1));
}
__device__ __forceinline__ void mma_bf16(float& d0, float& d1, float& d2, float& d3,
                                         uint32_t a0, uint32_t a1, uint32_t a2, uint32_t a3,
                                         uint32_t b0, uint32_t b1) {
    asm volatile("mma.sync.aligned.m16n8k16.row.col.f32.bf16.bf16.f32 "
                 "{%0,%1,%2,%3},{%4,%5,%6,%7},{%8,%9},{%0,%1,%2,%3};"
                 : "+f"(d0), "+f"(d1), "+f"(d2), "+f"(d3)
                 : "r"(a0), "r"(a1), "r"(a2), "r"(a3), "r"(b0), "r"(b1));
}
__device__ __forceinline__ void ldsm_x4(uint32_t& r0, uint32_t& r1, uint32_t& r2, uint32_t& r3,
                                        uint32_t addr) {
    asm volatile("ldmatrix.sync.aligned.m8n8.x4.shared.b16 {%0,%1,%2,%3}, [%4];"
                 : "=r"(r0), "=r"(r1), "=r"(r2), "=r"(r3) : "r"(addr));
}
__device__ __forceinline__ void ldsm_x4t(uint32_t& r0, uint32_t& r1, uint32_t& r2, uint32_t& r3,
                                         uint32_t addr) {
    asm volatile("ldmatrix.sync.aligned.m8n8.x4.trans.shared.b16 {%0,%1,%2,%3}, [%4];"
                 : "=r"(r0), "=r"(r1), "=r"(r2), "=r"(r3) : "r"(addr));
}
__device__ __forceinline__ void cp_async16(uint32_t saddr, const void* gaddr, int srcsize) {
    asm volatile("cp.async.ca.shared.global [%0], [%1], 16, %2;"
                 :: "r"(saddr), "l"(gaddr), "r"(srcsize) : "memory");
}
__device__ __forceinline__ void cp_async16f(uint32_t saddr, const void* gaddr) {
    asm volatile("cp.async.ca.shared.global [%0], [%1], 16;"
                 :: "r"(saddr), "l"(gaddr) : "memory");
}
__device__ __forceinline__ void cp_commit() {
    asm volatile("cp.async.commit_group;" ::: "memory");
}
template<int N> __device__ __forceinline__ void cp_wait() {
    asm volatile("cp.async.wait_group %0;" :: "n"(N) : "memory");
}

// ---------------- 0a) mask canonicalization (dtype auto-detect), frag-ordered ----------------
__global__ __launch_bounds__(256)
void mask_kernel(const unsigned char* __restrict__ mraw) {
    __shared__ int s_pos[4];
    if (threadIdx.x < 4) s_pos[threadIdx.x] = 0;
    __syncthreads();
    int loc[4] = {0, 0, 0, 0};
    for (int i = threadIdx.x; i < 4096; i += blockDim.x)
        if (mraw[i]) loc[i & 3] = 1;
    #pragma unroll
    for (int p = 0; p < 4; p++)
        if (loc[p]) atomicOr(&s_pos[p], 1);
    __syncthreads();
    int mode;                 // 0=uint8, 1=int32, 2=float32
    if (s_pos[1]) mode = 0;
    else if (s_pos[2] | s_pos[3]) mode = 2;
    else mode = 1;
    const int total = B_ * NPAD;
    for (int idx = blockIdx.x * blockDim.x + threadIdx.x; idx < total;
         idx += gridDim.x * blockDim.x) {
        int b = idx / NPAD;
        int j = idx - b * NPAD;
        float v = -3e38f;
        if (j < NSEQ) {
            int i = b * NSEQ + j;
            bool mm;
            if (mode == 0)      mm = mraw[i] != 0;
            else if (mode == 1) mm = ((const int*)mraw)[i] != 0;
            else                mm = ((const float*)mraw)[i] != 0.f;
            v = mm ? -3e38f : 0.f;
        }
        int rem = j & 127;
        int nt = rem >> 3, tt = (rem >> 1) & 3, e = rem & 1;
        g_madd[b * NPAD + (j & ~127) + tt * 32 + nt * 2 + e] = v;
    }
}

// ---------------- 0b) weight tf32 round + k-permute (both matrices, one launch) ----------------
#define WQ4 (768 * 256 / 4)
#define WP4 (256 * 256 / 4)
__global__ void roundw_kernel(const float* __restrict__ wq, const float* __restrict__ wp) {
    int i = blockIdx.x * blockDim.x + threadIdx.x;
    const float* src;
    float* dst;
    if (i < WQ4) { src = wq; dst = g_wq; }
    else if (i < WQ4 + WP4) { src = wp; dst = g_wp; i -= WQ4; }
    else return;
    float4 v = ((const float4*)src)[i];
    int base = i * 4;
    int row = base >> 8, kk = base & 255;
    int c32 = kk & ~31, rem = kk & 31;
    int ks = rem >> 3, h = (rem >> 2) & 1;
    float vals[4] = {tf32r(v.x), tf32r(v.y), tf32r(v.z), tf32r(v.w)};
    #pragma unroll
    for (int j = 0; j < 4; j++)
        dst[(size_t)row * 256 + c32 + j * 8 + ks * 2 + h] = vals[j];
}

// ---------------- 1) bias gather, write-coalesced ----------------
__global__ __launch_bounds__(256)
void bias_kernel(const int* __restrict__ rel_index,
                 const float* __restrict__ rpb, int num_rel) {
    const int i = blockIdx.x;
    const int* rrow = rel_index + (size_t)i * NSEQ;
    for (int p32 = threadIdx.x; p32 < NPAD / 2; p32 += 256) {
        int pos = p32 * 2;
        int base = pos & ~127;
        int rem  = pos & 127;
        int nt = (rem & 31) >> 1;
        int tt = rem >> 5;
        int j0 = base + nt * 8 + 2 * tt;
        bool in = (j0 + 1) < NSEQ;
        int r0 = 0, r1 = 0;
        if (in) { r0 = rrow[j0]; r1 = rrow[j0 + 1]; }
        #pragma unroll
        for (int h = 0; h < H_; h++) {
            uint32_t w = 0;
            if (in)
                w = pack_bf16(rpb[h * num_rel + r0] * LOG2E,
                              rpb[h * num_rel + r1] * LOG2E);
            *(uint32_t*)&g_bias[((size_t)h * NSEQ + i) * NPAD + pos] = w;
        }
    }
}

// ---------------- 2/4) tf32 GEMM, cp.async pipelined, permuted-W B fragments ----------------
#define GP 36
#define G_STAGE 36864
#define GEMM_SMEM 73728

template<int MODE>
__global__ __launch_bounds__(256, 2)
void gemm_tf32(const float* __restrict__ A, const float* __restrict__ W,
               const float* __restrict__ bias, float* __restrict__ Cout, int Ntotal) {
    extern __shared__ float sm[];
    const uint32_t sbase = (uint32_t)__cvta_generic_to_shared(sm);
    const int tid  = threadIdx.x;
    const int warp = tid >> 5, lane = tid & 31;
    const int g = lane >> 2, t = lane & 3;
    const int wm = warp >> 1, wn = warp & 1;
    const int bm = blockIdx.x, bn = blockIdx.y;

    const float* Abase = A + (size_t)(bm * 128) * 256;
    const float* Wbase = W + (size_t)(bn * 128) * 256;

    auto stage = [&](int kc, int p) {
        #pragma unroll
        for (int it = 0; it < 4; it++) {
            int idx = tid + it * 256;
            int row = idx >> 3, ch = idx & 7;
            uint32_t sA = sbase + p * G_STAGE + row * (GP * 4) + ch * 16;
            cp_async16f(sA,         Abase + (size_t)row * 256 + kc * 32 + ch * 4);
            cp_async16f(sA + 18432, Wbase + (size_t)row * 256 + kc * 32 + ch * 4);
        }
        cp_commit();
    };

    float acc[2][8][4];
    #pragma unroll
    for (int i = 0; i < 2; i++)
        #pragma unroll
        for (int j = 0; j < 8; j++)
            #pragma unroll
            for (int k = 0; k < 4; k++) acc[i][j][k] = 0.f;

    stage(0, 0);
    for (int kc = 0; kc < 8; kc++) {
        int p = kc & 1;
        cp_wait<0>();
        __syncthreads();
        if (kc < 7) stage(kc + 1, p ^ 1);
        const float* As = sm + p * (G_STAGE / 4);
        const float* Bs = As + 18432 / 4;

        uint32_t aF[2][4][4];
        #pragma unroll
        for (int mt = 0; mt < 2; mt++) {
            int m0 = wm * 32 + mt * 16;
            #pragma unroll
            for (int ks = 0; ks < 4; ks++) {
                int k0 = ks * 8;
                if (MODE == 0) {
                    aF[mt][ks][0] = __float_as_uint(tf32r(As[(m0 + g    ) * GP + k0 + t    ]));
                    aF[mt][ks][1] = __float_as_uint(tf32r(As[(m0 + g + 8) * GP + k0 + t    ]));
                    aF[mt][ks][2] = __float_as_uint(tf32r(As[(m0 + g    ) * GP + k0 + t + 4]));
                    aF[mt][ks][3] = __float_as_uint(tf32r(As[(m0 + g + 8) * GP + k0 + t + 4]));
                } else {
                    aF[mt][ks][0] = __float_as_uint(As[(m0 + g    ) * GP + k0 + t    ]);
                    aF[mt][ks][1] = __float_as_uint(As[(m0 + g + 8) * GP + k0 + t    ]);
                    aF[mt][ks][2] = __float_as_uint(As[(m0 + g    ) * GP + k0 + t + 4]);
                    aF[mt][ks][3] = __float_as_uint(As[(m0 + g + 8) * GP + k0 + t + 4]);
                }
            }
        }
        #pragma unroll
        for (int np = 0; np < 4; np++) {
            uint4 bv[2][2];
            #pragma unroll
            for (int e = 0; e < 2; e++) {
                int n0 = wn * 64 + (np * 2 + e) * 8;
                const float4* bp = (const float4*)&Bs[(n0 + g) * GP + 8 * t];
                bv[e][0] = *(const uint4*)&bp[0];
                bv[e][1] = *(const uint4*)&bp[1];
            }
            #pragma unroll
            for (int ks = 0; ks < 4; ks++) {
                #pragma unroll
                for (int e = 0; e < 2; e++) {
                    int nt = np * 2 + e;
                    uint32_t b0 = u4w(bv[e][ks >> 1], (ks & 1) * 2);
                    uint32_t b1 = u4w(bv[e][ks >> 1], (ks & 1) * 2 + 1);
                    mma_tf32(acc[0][nt][0], acc[0][nt][1], acc[0][nt][2], acc[0][nt][3],
                             aF[0][ks][0], aF[0][ks][1], aF[0][ks][2], aF[0][ks][3], b0, b1);
                    mma_tf32(acc[1][nt][0], acc[1][nt][1], acc[1][nt][2], acc[1][nt][3],
                             aF[1][ks][0], aF[1][ks][1], aF[1][ks][2], aF[1][ks][3], b0, b1);
                }
            }
        }
        __syncthreads();
    }

    if (MODE == 0) {
        const int which = bn >> 1;
        __nv_bfloat16* dst = (which == 0) ? g_q : (which == 1) ? g_k : g_v;
        const float sc = (which == 0) ? QK_SCALE : 1.f;
        #pragma unroll
        for (int mt = 0; mt < 2; mt++) {
            int r0 = bm * 128 + wm * 32 + mt * 16 + g;
            int r8 = r0 + 8;
            int b0i = r0 / NSEQ, n0 = r0 - b0i * NSEQ;
            int b8i = r8 / NSEQ, n8 = r8 - b8i * NSEQ;
            #pragma unroll
            for (int nt = 0; nt < 8; nt++) {
                int c0 = bn * 128 + wn * 64 + nt * 8 + 2 * t;
                int h = (c0 >> 5) & 7, d = c0 & 31;
                uint32_t lo = pack_bf16(acc[mt][nt][0] * sc, acc[mt][nt][1] * sc);
                uint32_t hi = pack_bf16(acc[mt][nt][2] * sc, acc[mt][nt][3] * sc);
                *(uint32_t*)&dst[((size_t)(b0i * 8 + h) * NSEQ + n0) * 32 + d] = lo;
                *(uint32_t*)&dst[((size_t)(b8i * 8 + h) * NSEQ + n8) * 32 + d] = hi;
            }
        }
    } else {
        #pragma unroll
        for (int mt = 0; mt < 2; mt++) {
            int r0 = bm * 128 + wm * 32 + mt * 16 + g;
            #pragma unroll
            for (int nt = 0; nt < 8; nt++) {
                int c0 = bn * 128 + wn * 64 + nt * 8 + 2 * t;
                float bb0 = bias[c0], bb1 = bias[c0 + 1];
                float2 v0 = make_float2(acc[mt][nt][0] + bb0, acc[mt][nt][1] + bb1);
                float2 v1 = make_float2(acc[mt][nt][2] + bb0, acc[mt][nt][3] + bb1);
                *(float2*)&Cout[(size_t)r0       * Ntotal + c0] = v0;
                *(float2*)&Cout[(size_t)(r0 + 8) * Ntotal + c0] = v1;
            }
        }
    }
}

// ---------------- 3) flash attention: 4 warps x 64 Q-rows, 16-key chunks ----------------
#define KV_PITCH 80
#define SM_STAGE 20480
#define ATTN_SMEM 40960

__global__ void __launch_bounds__(128, 2) attn_kernel() {
    extern __shared__ char smx[];
    const uint32_t sbase = (uint32_t)__cvta_generic_to_shared(smx);

    const int tid  = threadIdx.x;
    const int warp = tid >> 5, lane = tid & 31;
    const int g = lane >> 2, t = lane & 3;
    const int qt = blockIdx.x, bh = blockIdx.y;
    const int b = bh >> 3, h = bh & 7;
    const int qbase = qt * 256;

    // 8 rows per thread: sub 0..3 (m16 tiles) x {g, g+8}
    int r[8], rcl[8];
    #pragma unroll
    for (int i = 0; i < 8; i++) {
        r[i]  = qbase + warp * 64 + (i >> 1) * 16 + g + (i & 1) * 8;
        rcl[i] = min(r[i], NSEQ - 1);
    }

    const __nv_bfloat16* kbase = g_k + (size_t)bh * NSEQ * 32;
    const __nv_bfloat16* vbase = g_v + (size_t)bh * NSEQ * 32;

    // Q fragments: aq[sub][kk][frag]
    uint32_t aq[4][2][4];
    #pragma unroll
    for (int sub = 0; sub < 4; sub++) {
        const __nv_bfloat16* qlo = g_q + ((size_t)bh * NSEQ + rcl[2 * sub])     * 32;
        const __nv_bfloat16* qhi = g_q + ((size_t)bh * NSEQ + rcl[2 * sub + 1]) * 32;
        #pragma unroll
        for (int kk = 0; kk < 2; kk++) {
            aq[sub][kk][0] = *(const uint32_t*)(qlo + kk * 16 + 2 * t);
            aq[sub][kk][1] = *(const uint32_t*)(qhi + kk * 16 + 2 * t);
            aq[sub][kk][2] = *(const uint32_t*)(qlo + kk * 16 + 2 * t + 8);
            aq[sub][kk][3] = *(const uint32_t*)(qhi + kk * 16 + 2 * t + 8);
        }
    }

    // frag-ordered bias row pointers (t*32 included) and mask pointer (t*32 included)
    const __nv_bfloat16* bptr[8];
    #pragma unroll
    for (int i = 0; i < 8; i++)
        bptr[i] = g_bias + ((size_t)h * NSEQ + rcl[i]) * NPAD + t * 32;
    const float* mptr = g_madd + b * NPAD + t * 32;

    const uint32_t lk_row = (lane & 7);
    const uint32_t lk_grp = (lane >> 3);
    const uint32_t offK = lk_row * KV_PITCH + lk_grp * 16;
    const uint32_t offV = ((lk_grp & 1) * 8 + lk_row) * KV_PITCH + (lk_grp >> 1) * 16 + 10240;

    float accO[4][4][4];
    #pragma unroll
    for (int s = 0; s < 4; s++)
        #pragma unroll
        for (int i = 0; i < 4; i++)
            #pragma unroll
            for (int j = 0; j < 4; j++) accO[s][i][j] = 0.f;
    float l[8] = {0.f, 0.f, 0.f, 0.f, 0.f, 0.f, 0.f, 0.f};

    auto stage = [&](int kt, int p) {
        const int kb = kt * 128;
        #pragma unroll
        for (int it = 0; it < 4; it++) {
            int idx = tid + it * 128;
            int row = idx >> 2, ch = idx & 3;
            int key = kb + row;
            int sz = (key < NSEQ) ? 16 : 0;
            uint32_t s0 = sbase + p * SM_STAGE + row * KV_PITCH + ch * 16;
            cp_async16(s0,         kbase + (size_t)key * 32 + ch * 8, sz);
            cp_async16(s0 + 10240, vbase + (size_t)key * 32 + ch * 8, sz);
        }
        cp_commit();
    };

    stage(0, 0);

    for (int kt = 0; kt < 10; kt++) {
        const int p  = kt & 1;
        const int kb = kt * 128;
        cp_wait<0>();
        __syncthreads();
        if (kt < 9) stage(kt + 1, p ^ 1);

        const uint32_t addrK = sbase + p * SM_STAGE + offK;
        const uint32_t addrV = sbase + p * SM_STAGE + offV;

        #pragma unroll
        for (int c = 0; c < 8; c++) {            // 16-key chunks
            // --- S init = bias + mask (positions t*32 + 4c..4c+3; ptrs include t*32) ---
            float S[4][2][4];
            {
                float4 mm = *(const float4*)(mptr + kb + c * 4);
                #pragma unroll
                for (int sub = 0; sub < 4; sub++) {
                    uint2 blo = *(const uint2*)(bptr[2 * sub]     + kb + c * 4);
                    uint2 bhi = *(const uint2*)(bptr[2 * sub + 1] + kb + c * 4);
                    float2 l0 = unpack_bf16(blo.x), l1 = unpack_bf16(blo.y);
                    float2 h0 = unpack_bf16(bhi.x), h1 = unpack_bf16(bhi.y);
                    S[sub][0][0] = l0.x + mm.x;  S[sub][0][1] = l0.y + mm.y;
                    S[sub][0][2] = h0.x + mm.x;  S[sub][0][3] = h0.y + mm.y;
                    S[sub][1][0] = l1.x + mm.z;  S[sub][1][1] = l1.y + mm.w;
                    S[sub][1][2] = h1.x + mm.z;  S[sub][1][3] = h1.y + mm.w;
                }
            }
            // --- S += Q K^T (2 ldsm feed 16 MMAs) ---
            #pragma unroll
            for (int ntl = 0; ntl < 2; ntl++) {
                uint32_t b0, b1, b2, b3;
                ldsm_x4(b0, b1, b2, b3, addrK + (c * 2 + ntl) * (8 * KV_PITCH));
                #pragma unroll
                for (int sub = 0; sub < 4; sub++) {
                    mma_bf16(S[sub][ntl][0], S[sub][ntl][1], S[sub][ntl][2], S[sub][ntl][3],
                             aq[sub][0][0], aq[sub][0][1], aq[sub][0][2], aq[sub][0][3], b0, b1);
                    mma_bf16(S[sub][ntl][0], S[sub][ntl][1], S[sub][ntl][2], S[sub][ntl][3],
                             aq[sub][1][0], aq[sub][1][1], aq[sub][1][2], aq[sub][1][3], b2, b3);
                }
            }
            // --- P = exp2(S); row sums; pack A frags ---
            uint32_t a[4][4];
            #pragma unroll
            for (int sub = 0; sub < 4; sub++) {
                #pragma unroll
                for (int ntl = 0; ntl < 2; ntl++) {
                    S[sub][ntl][0] = ex2f(S[sub][ntl][0]);
                    S[sub][ntl][1] = ex2f(S[sub][ntl][1]);
                    S[sub][ntl][2] = ex2f(S[sub][ntl][2]);
                    S[sub][ntl][3] = ex2f(S[sub][ntl][3]);
                    l[2 * sub]     += S[sub][ntl][0] + S[sub][ntl][1];
                    l[2 * sub + 1] += S[sub][ntl][2] + S[sub][ntl][3];
                }
                a[sub][0] = pack_bf16(S[sub][0][0], S[sub][0][1]);
                a[sub][1] = pack_bf16(S[sub][0][2], S[sub][0][3]);
                a[sub][2] = pack_bf16(S[sub][1][0], S[sub][1][1]);
                a[sub][3] = pack_bf16(S[sub][1][2], S[sub][1][3]);
            }
            // --- O += P V (2 ldsm feed 16 MMAs) ---
            #pragma unroll
            for (int nob = 0; nob < 4; nob += 2) {
                uint32_t v0, v1, v2, v3;
                ldsm_x4t(v0, v1, v2, v3, addrV + c * (16 * KV_PITCH) + nob * 16);
                #pragma unroll
                for (int sub = 0; sub < 4; sub++) {
                    mma_bf16(accO[sub][nob][0], accO[sub][nob][1],
                             accO[sub][nob][2], accO[sub][nob][3],
                             a[sub][0], a[sub][1], a[sub][2], a[sub][3], v0, v1);
                    mma_bf16(accO[sub][nob + 1][0], accO[sub][nob + 1][1],
                             accO[sub][nob + 1][2], accO[sub][nob + 1][3],
                             a[sub][0], a[sub][1], a[sub][2], a[sub][3], v2, v3);
                }
            }
        }
    }

    #pragma unroll
    for (int i = 0; i < 8; i++) {
        l[i] += __shfl_xor_sync(0xffffffffu, l[i], 1);
        l[i] += __shfl_xor_sync(0xffffffffu, l[i], 2);
    }

    // outputs tf32-rounded: proj GEMM consumes g_att without further rounding
    #pragma unroll
    for (int sub = 0; sub < 4; sub++) {
        float il = 1.f / l[2 * sub];
        float ih = 1.f / l[2 * sub + 1];
        if (r[2 * sub] < NSEQ) {
            #pragma unroll
            for (int no = 0; no < 4; no++) {
                float2 v = make_float2(tf32r(accO[sub][no][0] * il), tf32r(accO[sub][no][1] * il));
                *(float2*)&g_att[((size_t)b * NSEQ + r[2 * sub]) * 256 + h * 32 + no * 8 + 2 * t] = v;
            }
        }
        if (r[2 * sub + 1] < NSEQ) {
            #pragma unroll
            for (int no = 0; no < 4; no++) {
                float2 v = make_float2(tf32r(accO[sub][no][2] * ih), tf32r(accO[sub][no][3] * ih));
                *(float2*)&g_att[((size_t)b * NSEQ + r[2 * sub + 1]) * 256 + h * 32 + no * 8 + 2 * t] = v;
            }
        }
    }
}

// ---------------- launch ----------------
extern "C" void kernel_launch(void* const* d_in, const int* in_sizes, int n_in,
                              void* d_out, int out_size) {
    const float*         x       = (const float*)d_in[0];
    const unsigned char* mask    = (const unsigned char*)d_in[1];
    const float*         w_qkv   = (const float*)d_in[2];
    const float*         w_proj  = (const float*)d_in[3];
    const float*         b_proj  = (const float*)d_in[4];
    const float*         rpb     = (const float*)d_in[5];
    const int*           relidx  = (const int*)d_in[6];
    const int num_rel = in_sizes[5] / H_;

    cudaFuncSetAttribute(gemm_tf32<0>, cudaFuncAttributeMaxDynamicSharedMemorySize, GEMM_SMEM);
    cudaFuncSetAttribute(gemm_tf32<1>, cudaFuncAttributeMaxDynamicSharedMemorySize, GEMM_SMEM);
    cudaFuncSetAttribute(attn_kernel,  cudaFuncAttributeMaxDynamicSharedMemorySize, ATTN_SMEM);

    void *p_att = nullptr, *p_wq = nullptr, *p_wp = nullptr;
    cudaGetSymbolAddress(&p_att, g_att);
    cudaGetSymbolAddress(&p_wq,  g_wq);
    cudaGetSymbolAddress(&p_wp,  g_wp);

    mask_kernel<<<40, 256>>>(mask);
    roundw_kernel<<<(WQ4 + WP4 + 255) / 256, 256>>>(w_qkv, w_proj);
    bias_kernel<<<NSEQ, 256>>>(relidx, rpb, num_rel);
    gemm_tf32<0><<<dim3(MROWS / 128, 768 / 128), 256, GEMM_SMEM>>>(
        x, (const float*)p_wq, nullptr, nullptr, 768);
    attn_kernel<<<dim3(5, B_ * H_), 128, ATTN_SMEM>>>();
    gemm_tf32<1><<<dim3(MROWS / 128, 256 / 128), 256, GEMM_SMEM>>>(
        (const float*)p_att, (const float*)p_wp, b_proj, (float*)d_out, 256);
}

// round 15
// speedup vs baseline: 1.2030x; 1.2030x over previous
#include <cuda_runtime.h>
#include <cuda_bf16.h>
#include <cstdint>

#define B_    16
#define NSEQ  1168
#define H_    8
#define DH    32
#define C_    256
#define NPAD  1280
#define MROWS (B_*NSEQ)   // 18688 = 146*128
#define LOG2E 1.4426950408889634f
#define QK_SCALE (0.1767766952966369f * LOG2E)   // 32^-0.5 * log2(e), folded into q

// ---------------- scratch (device globals; no runtime alloc) ----------------
__device__ __align__(16) __nv_bfloat16  g_q[(size_t)B_ * H_ * NSEQ * DH];
__device__ __align__(16) __nv_bfloat16  g_k[(size_t)B_ * H_ * NSEQ * DH];
__device__ __align__(16) __nv_bfloat16  g_v[(size_t)B_ * H_ * NSEQ * DH];
__device__ __align__(16) __nv_bfloat16  g_bias[(size_t)H_ * NSEQ * NPAD];  // frag-ordered, *log2e
__device__ __align__(16) float g_att[(size_t)MROWS * C_];     // tf32-rounded by attn epilogue
__device__ __align__(16) float g_madd[(size_t)B_ * NPAD];     // frag-ordered additive mask
__device__ __align__(16) float g_wq[768 * 256];               // tf32-rounded, k-permuted w_qkv
__device__ __align__(16) float g_wp[256 * 256];               // tf32-rounded, k-permuted w_proj

// ---------------- helpers ----------------
__device__ __forceinline__ float tf32r(float x) {
    uint32_t u;
    asm("cvt.rna.tf32.f32 %0, %1;" : "=r"(u) : "f"(x));
    return __uint_as_float(u);
}
__device__ __forceinline__ float ex2f(float x) {
    float y;
    asm("ex2.approx.ftz.f32 %0, %1;" : "=f"(y) : "f"(x));
    return y;
}
__device__ __forceinline__ uint32_t pack_bf16(float x, float y) {
    __nv_bfloat162 h = __floats2bfloat162_rn(x, y);
    return *reinterpret_cast<uint32_t*>(&h);
}
__device__ __forceinline__ float2 unpack_bf16(uint32_t u) {
    __nv_bfloat162 h = *reinterpret_cast<__nv_bfloat162*>(&u);
    return __bfloat1622float2(h);
}
__device__ __forceinline__ uint32_t u4w(const uint4& v, int w) {
    return w == 0 ? v.x : w == 1 ? v.y : w == 2 ? v.z : v.w;
}
__device__ __forceinline__ void mma_tf32(float& d0, float& d1, float& d2, float& d3,
                                         uint32_t a0, uint32_t a1, uint32_t a2, uint32_t a3,
                                         uint32_t b0, uint32_t b1) {
    asm volatile("mma.sync.aligned.m16n8k8.row.col.f32.tf32.tf32.f32 "
                 "{%0,%1,%2,%3},{%4,%5,%6,%7},{%8,%9},{%0,%1,%2,%3};"
                 : "+f"(d0), "+f"(d1), "+f"(d2), "+f"(d3)
                 : "r"(a0), "r"(a1), "r"(a2), "r"(a3), "r"(b0), "r"(b1));
}
__device__ __forceinline__ void mma_bf16(float& d0, float& d1, float& d2, float& d3,
                                         uint32_t a0, uint32_t a1, uint32_t a2, uint32_t a3,
                                         uint32_t b0, uint32_t b1) {
    asm volatile("mma.sync.aligned.m16n8k16.row.col.f32.bf16.bf16.f32 "
                 "{%0,%1,%2,%3},{%4,%5,%6,%7},{%8,%9},{%0,%1,%2,%3};"
                 : "+f"(d0), "+f"(d1), "+f"(d2), "+f"(d3)
                 : "r"(a0), "r"(a1), "r"(a2), "r"(a3), "r"(b0), "r"(b1));
}
__device__ __forceinline__ void ldsm_x4(uint32_t& r0, uint32_t& r1, uint32_t& r2, uint32_t& r3,
                                        uint32_t addr) {
    asm volatile("ldmatrix.sync.aligned.m8n8.x4.shared.b16 {%0,%1,%2,%3}, [%4];"
                 : "=r"(r0), "=r"(r1), "=r"(r2), "=r"(r3) : "r"(addr));
}
__device__ __forceinline__ void ldsm_x4t(uint32_t& r0, uint32_t& r1, uint32_t& r2, uint32_t& r3,
                                         uint32_t addr) {
    asm volatile("ldmatrix.sync.aligned.m8n8.x4.trans.shared.b16 {%0,%1,%2,%3}, [%4];"
                 : "=r"(r0), "=r"(r1), "=r"(r2), "=r"(r3) : "r"(addr));
}
__device__ __forceinline__ void cp_async16(uint32_t saddr, const void* gaddr, int srcsize) {
    asm volatile("cp.async.ca.shared.global [%0], [%1], 16, %2;"
                 :: "r"(saddr), "l"(gaddr), "r"(srcsize) : "memory");
}
__device__ __forceinline__ void cp_async16f(uint32_t saddr, const void* gaddr) {
    asm volatile("cp.async.ca.shared.global [%0], [%1], 16;"
                 :: "r"(saddr), "l"(gaddr) : "memory");
}
__device__ __forceinline__ void cp_commit() {
    asm volatile("cp.async.commit_group;" ::: "memory");
}
template<int N> __device__ __forceinline__ void cp_wait() {
    asm volatile("cp.async.wait_group %0;" :: "n"(N) : "memory");
}

// ---------------- 0a) mask canonicalization (dtype auto-detect), frag-ordered ----------------
__global__ __launch_bounds__(256)
void mask_kernel(const unsigned char* __restrict__ mraw) {
    __shared__ int s_pos[4];
    if (threadIdx.x < 4) s_pos[threadIdx.x] = 0;
    __syncthreads();
    int loc[4] = {0, 0, 0, 0};
    for (int i = threadIdx.x; i < 4096; i += blockDim.x)
        if (mraw[i]) loc[i & 3] = 1;
    #pragma unroll
    for (int p = 0; p < 4; p++)
        if (loc[p]) atomicOr(&s_pos[p], 1);
    __syncthreads();
    int mode;                 // 0=uint8, 1=int32, 2=float32
    if (s_pos[1]) mode = 0;
    else if (s_pos[2] | s_pos[3]) mode = 2;
    else mode = 1;
    const int total = B_ * NPAD;
    for (int idx = blockIdx.x * blockDim.x + threadIdx.x; idx < total;
         idx += gridDim.x * blockDim.x) {
        int b = idx / NPAD;
        int j = idx - b * NPAD;
        float v = -3e38f;
        if (j < NSEQ) {
            int i = b * NSEQ + j;
            bool mm;
            if (mode == 0)      mm = mraw[i] != 0;
            else if (mode == 1) mm = ((const int*)mraw)[i] != 0;
            else                mm = ((const float*)mraw)[i] != 0.f;
            v = mm ? -3e38f : 0.f;
        }
        int rem = j & 127;
        int nt = rem >> 3, tt = (rem >> 1) & 3, e = rem & 1;
        g_madd[b * NPAD + (j & ~127) + tt * 32 + nt * 2 + e] = v;
    }
}

// ---------------- 0b) weight tf32 round + k-permute (both matrices, one launch) ----------------
#define WQ4 (768 * 256 / 4)
#define WP4 (256 * 256 / 4)
__global__ void roundw_kernel(const float* __restrict__ wq, const float* __restrict__ wp) {
    int i = blockIdx.x * blockDim.x + threadIdx.x;
    const float* src;
    float* dst;
    if (i < WQ4) { src = wq; dst = g_wq; }
    else if (i < WQ4 + WP4) { src = wp; dst = g_wp; i -= WQ4; }
    else return;
    float4 v = ((const float4*)src)[i];
    int base = i * 4;
    int row = base >> 8, kk = base & 255;
    int c32 = kk & ~31, rem = kk & 31;
    int ks = rem >> 3, h = (rem >> 2) & 1;
    float vals[4] = {tf32r(v.x), tf32r(v.y), tf32r(v.z), tf32r(v.w)};
    #pragma unroll
    for (int j = 0; j < 4; j++)
        dst[(size_t)row * 256 + c32 + j * 8 + ks * 2 + h] = vals[j];
}

// ---------------- 1) bias gather, write-coalesced ----------------
__global__ __launch_bounds__(256)
void bias_kernel(const int* __restrict__ rel_index,
                 const float* __restrict__ rpb, int num_rel) {
    const int i = blockIdx.x;
    const int* rrow = rel_index + (size_t)i * NSEQ;
    for (int p32 = threadIdx.x; p32 < NPAD / 2; p32 += 256) {
        int pos = p32 * 2;
        int base = pos & ~127;
        int rem  = pos & 127;
        int nt = (rem & 31) >> 1;
        int tt = rem >> 5;
        int j0 = base + nt * 8 + 2 * tt;
        bool in = (j0 + 1) < NSEQ;
        int r0 = 0, r1 = 0;
        if (in) { r0 = rrow[j0]; r1 = rrow[j0 + 1]; }
        #pragma unroll
        for (int h = 0; h < H_; h++) {
            uint32_t w = 0;
            if (in)
                w = pack_bf16(rpb[h * num_rel + r0] * LOG2E,
                              rpb[h * num_rel + r1] * LOG2E);
            *(uint32_t*)&g_bias[((size_t)h * NSEQ + i) * NPAD + pos] = w;
        }
    }
}

// ---------------- 2/4) tf32 GEMM, cp.async 3-stage pipeline, permuted-W B fragments ----------------
#define GP 36
#define G_STAGE 36864
#define GEMM_SMEM (3 * G_STAGE)   // 110592

template<int MODE>
__global__ __launch_bounds__(256, 2)
void gemm_tf32(const float* __restrict__ A, const float* __restrict__ W,
               const float* __restrict__ bias, float* __restrict__ Cout, int Ntotal) {
    extern __shared__ float sm[];
    const uint32_t sbase = (uint32_t)__cvta_generic_to_shared(sm);
    const int tid  = threadIdx.x;
    const int warp = tid >> 5, lane = tid & 31;
    const int g = lane >> 2, t = lane & 3;
    const int wm = warp >> 1, wn = warp & 1;
    const int bm = blockIdx.x, bn = blockIdx.y;

    const float* Abase = A + (size_t)(bm * 128) * 256;
    const float* Wbase = W + (size_t)(bn * 128) * 256;

    auto stage = [&](int kc, int p) {
        #pragma unroll
        for (int it = 0; it < 4; it++) {
            int idx = tid + it * 256;
            int row = idx >> 3, ch = idx & 7;
            uint32_t sA = sbase + p * G_STAGE + row * (GP * 4) + ch * 16;
            cp_async16f(sA,         Abase + (size_t)row * 256 + kc * 32 + ch * 4);
            cp_async16f(sA + 18432, Wbase + (size_t)row * 256 + kc * 32 + ch * 4);
        }
        cp_commit();
    };

    float acc[2][8][4];
    #pragma unroll
    for (int i = 0; i < 2; i++)
        #pragma unroll
        for (int j = 0; j < 8; j++)
            #pragma unroll
            for (int k = 0; k < 4; k++) acc[i][j][k] = 0.f;

    stage(0, 0);
    stage(1, 1);
    for (int kc = 0; kc < 8; kc++) {
        int p = kc % 3;
        if (kc < 7) cp_wait<1>(); else cp_wait<0>();
        __syncthreads();
        if (kc < 6) stage(kc + 2, (kc + 2) % 3);
        const float* As = sm + p * (G_STAGE / 4);
        const float* Bs = As + 18432 / 4;

        uint32_t aF[2][4][4];
        #pragma unroll
        for (int mt = 0; mt < 2; mt++) {
            int m0 = wm * 32 + mt * 16;
            #pragma unroll
            for (int ks = 0; ks < 4; ks++) {
                int k0 = ks * 8;
                if (MODE == 0) {
                    aF[mt][ks][0] = __float_as_uint(tf32r(As[(m0 + g    ) * GP + k0 + t    ]));
                    aF[mt][ks][1] = __float_as_uint(tf32r(As[(m0 + g + 8) * GP + k0 + t    ]));
                    aF[mt][ks][2] = __float_as_uint(tf32r(As[(m0 + g    ) * GP + k0 + t + 4]));
                    aF[mt][ks][3] = __float_as_uint(tf32r(As[(m0 + g + 8) * GP + k0 + t + 4]));
                } else {
                    aF[mt][ks][0] = __float_as_uint(As[(m0 + g    ) * GP + k0 + t    ]);
                    aF[mt][ks][1] = __float_as_uint(As[(m0 + g + 8) * GP + k0 + t    ]);
                    aF[mt][ks][2] = __float_as_uint(As[(m0 + g    ) * GP + k0 + t + 4]);
                    aF[mt][ks][3] = __float_as_uint(As[(m0 + g + 8) * GP + k0 + t + 4]);
                }
            }
        }
        #pragma unroll
        for (int np = 0; np < 4; np++) {
            uint4 bv[2][2];
            #pragma unroll
            for (int e = 0; e < 2; e++) {
                int n0 = wn * 64 + (np * 2 + e) * 8;
                const float4* bp = (const float4*)&Bs[(n0 + g) * GP + 8 * t];
                bv[e][0] = *(const uint4*)&bp[0];
                bv[e][1] = *(const uint4*)&bp[1];
            }
            #pragma unroll
            for (int ks = 0; ks < 4; ks++) {
                #pragma unroll
                for (int e = 0; e < 2; e++) {
                    int nt = np * 2 + e;
                    uint32_t b0 = u4w(bv[e][ks >> 1], (ks & 1) * 2);
                    uint32_t b1 = u4w(bv[e][ks >> 1], (ks & 1) * 2 + 1);
                    mma_tf32(acc[0][nt][0], acc[0][nt][1], acc[0][nt][2], acc[0][nt][3],
                             aF[0][ks][0], aF[0][ks][1], aF[0][ks][2], aF[0][ks][3], b0, b1);
                    mma_tf32(acc[1][nt][0], acc[1][nt][1], acc[1][nt][2], acc[1][nt][3],
                             aF[1][ks][0], aF[1][ks][1], aF[1][ks][2], aF[1][ks][3], b0, b1);
                }
            }
        }
        __syncthreads();
    }

    if (MODE == 0) {
        const int which = bn >> 1;
        __nv_bfloat16* dst = (which == 0) ? g_q : (which == 1) ? g_k : g_v;
        const float sc = (which == 0) ? QK_SCALE : 1.f;
        #pragma unroll
        for (int mt = 0; mt < 2; mt++) {
            int r0 = bm * 128 + wm * 32 + mt * 16 + g;
            int r8 = r0 + 8;
            int b0i = r0 / NSEQ, n0 = r0 - b0i * NSEQ;
            int b8i = r8 / NSEQ, n8 = r8 - b8i * NSEQ;
            #pragma unroll
            for (int nt = 0; nt < 8; nt++) {
                int c0 = bn * 128 + wn * 64 + nt * 8 + 2 * t;
                int h = (c0 >> 5) & 7, d = c0 & 31;
                uint32_t lo = pack_bf16(acc[mt][nt][0] * sc, acc[mt][nt][1] * sc);
                uint32_t hi = pack_bf16(acc[mt][nt][2] * sc, acc[mt][nt][3] * sc);
                *(uint32_t*)&dst[((size_t)(b0i * 8 + h) * NSEQ + n0) * 32 + d] = lo;
                *(uint32_t*)&dst[((size_t)(b8i * 8 + h) * NSEQ + n8) * 32 + d] = hi;
            }
        }
    } else {
        #pragma unroll
        for (int mt = 0; mt < 2; mt++) {
            int r0 = bm * 128 + wm * 32 + mt * 16 + g;
            #pragma unroll
            for (int nt = 0; nt < 8; nt++) {
                int c0 = bn * 128 + wn * 64 + nt * 8 + 2 * t;
                float bb0 = bias[c0], bb1 = bias[c0 + 1];
                float2 v0 = make_float2(acc[mt][nt][0] + bb0, acc[mt][nt][1] + bb1);
                float2 v1 = make_float2(acc[mt][nt][2] + bb0, acc[mt][nt][3] + bb1);
                *(float2*)&Cout[(size_t)r0       * Ntotal + c0] = v0;
                *(float2*)&Cout[(size_t)(r0 + 8) * Ntotal + c0] = v1;
            }
        }
    }
}

// ---------------- 3) flash attention (round-12 config): 4 warps x 32 Q-rows, 3-stage ----------------
#define KV_PITCH 80
#define SM_STAGE 20480
#define ATTN_SMEM (3 * SM_STAGE)  // 61440

__global__ void __launch_bounds__(128, 3) attn_kernel() {
    extern __shared__ char smx[];
    const uint32_t sbase = (uint32_t)__cvta_generic_to_shared(smx);

    const int tid  = threadIdx.x;
    const int warp = tid >> 5, lane = tid & 31;
    const int g = lane >> 2, t = lane & 3;
    const int qt = blockIdx.x, bh = blockIdx.y;
    const int b = bh >> 3, h = bh & 7;
    const int qbase = qt * 128;

    int r[4], rc[4];
    #pragma unroll
    for (int i = 0; i < 4; i++) {
        r[i]  = qbase + warp * 32 + g + i * 8;
        rc[i] = min(r[i], NSEQ - 1);
    }

    const __nv_bfloat16* kbase = g_k + (size_t)bh * NSEQ * 32;
    const __nv_bfloat16* vbase = g_v + (size_t)bh * NSEQ * 32;

    uint32_t aq[2][2][4];
    #pragma unroll
    for (int sub = 0; sub < 2; sub++) {
        const __nv_bfloat16* qlo = g_q + ((size_t)bh * NSEQ + rc[2 * sub])     * 32;
        const __nv_bfloat16* qhi = g_q + ((size_t)bh * NSEQ + rc[2 * sub + 1]) * 32;
        #pragma unroll
        for (int kk = 0; kk < 2; kk++) {
            aq[sub][kk][0] = *(const uint32_t*)(qlo + kk * 16 + 2 * t);
            aq[sub][kk][1] = *(const uint32_t*)(qhi + kk * 16 + 2 * t);
            aq[sub][kk][2] = *(const uint32_t*)(qlo + kk * 16 + 2 * t + 8);
            aq[sub][kk][3] = *(const uint32_t*)(qhi + kk * 16 + 2 * t + 8);
        }
    }

    const __nv_bfloat16* bptr[4];
    #pragma unroll
    for (int i = 0; i < 4; i++)
        bptr[i] = g_bias + ((size_t)h * NSEQ + rc[i]) * NPAD + t * 32;
    const float* mptr = g_madd + b * NPAD + t * 32;

    const uint32_t lk_row = (lane & 7);
    const uint32_t lk_grp = (lane >> 3);
    const uint32_t offK = lk_row * KV_PITCH + lk_grp * 16;
    const uint32_t offV = ((lk_grp & 1) * 8 + lk_row) * KV_PITCH + (lk_grp >> 1) * 16 + 10240;

    float accO[2][4][4];
    #pragma unroll
    for (int s = 0; s < 2; s++)
        #pragma unroll
        for (int i = 0; i < 4; i++)
            #pragma unroll
            for (int j = 0; j < 4; j++) accO[s][i][j] = 0.f;
    float l[4] = {0.f, 0.f, 0.f, 0.f};

    auto stage = [&](int kt, int p) {
        const int kb = kt * 128;
        #pragma unroll
        for (int it = 0; it < 4; it++) {
            int idx = tid + it * 128;
            int row = idx >> 2, ch = idx & 3;
            int key = kb + row;
            int sz = (key < NSEQ) ? 16 : 0;
            uint32_t s0 = sbase + p * SM_STAGE + row * KV_PITCH + ch * 16;
            cp_async16(s0,         kbase + (size_t)key * 32 + ch * 8, sz);
            cp_async16(s0 + 10240, vbase + (size_t)key * 32 + ch * 8, sz);
        }
        cp_commit();
    };

    stage(0, 0);
    stage(1, 1);

    for (int kt = 0; kt < 10; kt++) {
        const int p  = kt % 3;
        const int kb = kt * 128;
        if (kt < 9) cp_wait<1>(); else cp_wait<0>();
        __syncthreads();
        if (kt < 8) stage(kt + 2, (kt + 2) % 3);

        const uint32_t addrK = sbase + p * SM_STAGE + offK;
        const uint32_t addrV = sbase + p * SM_STAGE + offV;

        #pragma unroll
        for (int half = 0; half < 2; half++) {
            float S[2][8][4];
            #pragma unroll
            for (int qq = 0; qq < 2; qq++) {
                uint4 bu[4];
                #pragma unroll
                for (int i = 0; i < 4; i++)
                    bu[i] = *(const uint4*)(bptr[i] + kb + half * 16 + qq * 8);
                float4 m0 = *(const float4*)(mptr + kb + half * 16 + qq * 8);
                float4 m1 = *(const float4*)(mptr + kb + half * 16 + qq * 8 + 4);
                #pragma unroll
                for (int w = 0; w < 4; w++) {
                    int ntl = qq * 4 + w;
                    float mx = (w == 0) ? m0.x : (w == 1) ? m0.z : (w == 2) ? m1.x : m1.z;
                    float my = (w == 0) ? m0.y : (w == 1) ? m0.w : (w == 2) ? m1.y : m1.w;
                    #pragma unroll
                    for (int sub = 0; sub < 2; sub++) {
                        float2 bl  = unpack_bf16(u4w(bu[2 * sub],     w));
                        float2 bh2 = unpack_bf16(u4w(bu[2 * sub + 1], w));
                        S[sub][ntl][0] = bl.x + mx;   S[sub][ntl][1] = bl.y + my;
                        S[sub][ntl][2] = bh2.x + mx;  S[sub][ntl][3] = bh2.y + my;
                    }
                }
            }
            #pragma unroll
            for (int ntl = 0; ntl < 8; ntl++) {
                uint32_t b0, b1, b2, b3;
                ldsm_x4(b0, b1, b2, b3, addrK + (half * 8 + ntl) * (8 * KV_PITCH));
                #pragma unroll
                for (int sub = 0; sub < 2; sub++) {
                    mma_bf16(S[sub][ntl][0], S[sub][ntl][1], S[sub][ntl][2], S[sub][ntl][3],
                             aq[sub][0][0], aq[sub][0][1], aq[sub][0][2], aq[sub][0][3], b0, b1);
                    mma_bf16(S[sub][ntl][0], S[sub][ntl][1], S[sub][ntl][2], S[sub][ntl][3],
                             aq[sub][1][0], aq[sub][1][1], aq[sub][1][2], aq[sub][1][3], b2, b3);
                }
            }
            #pragma unroll
            for (int ntl = 0; ntl < 8; ntl++) {
                #pragma unroll
                for (int sub = 0; sub < 2; sub++) {
                    S[sub][ntl][0] = ex2f(S[sub][ntl][0]);
                    S[sub][ntl][1] = ex2f(S[sub][ntl][1]);
                    S[sub][ntl][2] = ex2f(S[sub][ntl][2]);
                    S[sub][ntl][3] = ex2f(S[sub][ntl][3]);
                    l[2 * sub]     += S[sub][ntl][0] + S[sub][ntl][1];
                    l[2 * sub + 1] += S[sub][ntl][2] + S[sub][ntl][3];
                }
            }
            #pragma unroll
            for (int jl = 0; jl < 4; jl++) {
                uint32_t a[2][4];
                #pragma unroll
                for (int sub = 0; sub < 2; sub++) {
                    a[sub][0] = pack_bf16(S[sub][2 * jl][0],     S[sub][2 * jl][1]);
                    a[sub][1] = pack_bf16(S[sub][2 * jl][2],     S[sub][2 * jl][3]);
                    a[sub][2] = pack_bf16(S[sub][2 * jl + 1][0], S[sub][2 * jl + 1][1]);
                    a[sub][3] = pack_bf16(S[sub][2 * jl + 1][2], S[sub][2 * jl + 1][3]);
                }
                #pragma unroll
                for (int nob = 0; nob < 4; nob += 2) {
                    uint32_t v0, v1, v2, v3;
                    ldsm_x4t(v0, v1, v2, v3,
                             addrV + (half * 4 + jl) * (16 * KV_PITCH) + nob * 16);
                    #pragma unroll
                    for (int sub = 0; sub < 2; sub++) {
                        mma_bf16(accO[sub][nob][0], accO[sub][nob][1],
                                 accO[sub][nob][2], accO[sub][nob][3],
                                 a[sub][0], a[sub][1], a[sub][2], a[sub][3], v0, v1);
                        mma_bf16(accO[sub][nob + 1][0], accO[sub][nob + 1][1],
                                 accO[sub][nob + 1][2], accO[sub][nob + 1][3],
                                 a[sub][0], a[sub][1], a[sub][2], a[sub][3], v2, v3);
                    }
                }
            }
        }
    }

    #pragma unroll
    for (int i = 0; i < 4; i++) {
        l[i] += __shfl_xor_sync(0xffffffffu, l[i], 1);
        l[i] += __shfl_xor_sync(0xffffffffu, l[i], 2);
    }

    // outputs tf32-rounded: proj GEMM consumes g_att without further rounding
    #pragma unroll
    for (int sub = 0; sub < 2; sub++) {
        float il = 1.f / l[2 * sub];
        float ih = 1.f / l[2 * sub + 1];
        if (r[2 * sub] < NSEQ) {
            #pragma unroll
            for (int no = 0; no < 4; no++) {
                float2 v = make_float2(tf32r(accO[sub][no][0] * il), tf32r(accO[sub][no][1] * il));
                *(float2*)&g_att[((size_t)b * NSEQ + r[2 * sub]) * 256 + h * 32 + no * 8 + 2 * t] = v;
            }
        }
        if (r[2 * sub + 1] < NSEQ) {
            #pragma unroll
            for (int no = 0; no < 4; no++) {
                float2 v = make_float2(tf32r(accO[sub][no][2] * ih), tf32r(accO[sub][no][3] * ih));
                *(float2*)&g_att[((size_t)b * NSEQ + r[2 * sub + 1]) * 256 + h * 32 + no * 8 + 2 * t] = v;
            }
        }
    }
}

// ---------------- launch ----------------
extern "C" void kernel_launch(void* const* d_in, const int* in_sizes, int n_in,
                              void* d_out, int out_size) {
    const float*         x       = (const float*)d_in[0];
    const unsigned char* mask    = (const unsigned char*)d_in[1];
    const float*         w_qkv   = (const float*)d_in[2];
    const float*         w_proj  = (const float*)d_in[3];
    const float*         b_proj  = (const float*)d_in[4];
    const float*         rpb     = (const float*)d_in[5];
    const int*           relidx  = (const int*)d_in[6];
    const int num_rel = in_sizes[5] / H_;

    cudaFuncSetAttribute(gemm_tf32<0>, cudaFuncAttributeMaxDynamicSharedMemorySize, GEMM_SMEM);
    cudaFuncSetAttribute(gemm_tf32<1>, cudaFuncAttributeMaxDynamicSharedMemorySize, GEMM_SMEM);
    cudaFuncSetAttribute(attn_kernel,  cudaFuncAttributeMaxDynamicSharedMemorySize, ATTN_SMEM);

    void *p_att = nullptr, *p_wq = nullptr, *p_wp = nullptr;
    cudaGetSymbolAddress(&p_att, g_att);
    cudaGetSymbolAddress(&p_wq,  g_wq);
    cudaGetSymbolAddress(&p_wp,  g_wp);

    mask_kernel<<<40, 256>>>(mask);
    roundw_kernel<<<(WQ4 + WP4 + 255) / 256, 256>>>(w_qkv, w_proj);
    bias_kernel<<<NSEQ, 256>>>(relidx, rpb, num_rel);
    gemm_tf32<0><<<dim3(MROWS / 128, 768 / 128), 256, GEMM_SMEM>>>(
        x, (const float*)p_wq, nullptr, nullptr, 768);
    attn_kernel<<<dim3(10, B_ * H_), 128, ATTN_SMEM>>>();
    gemm_tf32<1><<<dim3(MROWS / 128, 256 / 128), 256, GEMM_SMEM>>>(
        (const float*)p_att, (const float*)p_wp, b_proj, (float*)d_out, 256);
}

// round 16
// speedup vs baseline: 1.3257x; 1.1020x over previous
#include <cuda_runtime.h>
#include <cuda_bf16.h>
#include <cstdint>

#define B_    16
#define NSEQ  1168
#define H_    8
#define DH    32
#define C_    256
#define NPAD  1280
#define MROWS (B_*NSEQ)   // 18688 = 146*128
#define LOG2E 1.4426950408889634f
#define QK_SCALE (0.1767766952966369f * LOG2E)   // 32^-0.5 * log2(e), folded into q

// ---------------- scratch (device globals; no runtime alloc) ----------------
__device__ __align__(16) __nv_bfloat16  g_q[(size_t)B_ * H_ * NSEQ * DH];
__device__ __align__(16) __nv_bfloat16  g_k[(size_t)B_ * H_ * NSEQ * DH];
__device__ __align__(16) __nv_bfloat16  g_v[(size_t)B_ * H_ * NSEQ * DH];
__device__ __align__(16) __nv_bfloat16  g_bias[(size_t)H_ * NSEQ * NPAD];  // frag-ordered, *log2e
__device__ __align__(16) float g_att[(size_t)MROWS * C_];     // tf32-rounded by attn epilogue
__device__ __align__(16) float g_madd[(size_t)B_ * NPAD];     // frag-ordered additive mask
__device__ __align__(16) float g_wq[768 * 256];               // tf32-rounded, k-permuted w_qkv
__device__ __align__(16) float g_wp[256 * 256];               // tf32-rounded, k-permuted w_proj

// ---------------- helpers ----------------
__device__ __forceinline__ float tf32r(float x) {
    uint32_t u;
    asm("cvt.rna.tf32.f32 %0, %1;" : "=r"(u) : "f"(x));
    return __uint_as_float(u);
}
__device__ __forceinline__ float ex2f(float x) {
    float y;
    asm("ex2.approx.ftz.f32 %0, %1;" : "=f"(y) : "f"(x));
    return y;
}
__device__ __forceinline__ uint32_t pack_bf16(float x, float y) {
    __nv_bfloat162 h = __floats2bfloat162_rn(x, y);
    return *reinterpret_cast<uint32_t*>(&h);
}
__device__ __forceinline__ float2 unpack_bf16(uint32_t u) {
    __nv_bfloat162 h = *reinterpret_cast<__nv_bfloat162*>(&u);
    return __bfloat1622float2(h);
}
__device__ __forceinline__ uint32_t u4w(const uint4& v, int w) {
    return w == 0 ? v.x : w == 1 ? v.y : w == 2 ? v.z : v.w;
}
__device__ __forceinline__ void mma_tf32(float& d0, float& d1, float& d2, float& d3,
                                         uint32_t a0, uint32_t a1, uint32_t a2, uint32_t a3,
                                         uint32_t b0, uint32_t b1) {
    asm volatile("mma.sync.aligned.m16n8k8.row.col.f32.tf32.tf32.f32 "
                 "{%0,%1,%2,%3},{%4,%5,%6,%7},{%8,%9},{%0,%1,%2,%3};"
                 : "+f"(d0), "+f"(d1), "+f"(d2), "+f"(d3)
                 : "r"(a0), "r"(a1), "r"(a2), "r"(a3), "r"(b0), "r"(b1));
}
__device__ __forceinline__ void mma_bf16(float& d0, float& d1, float& d2, float& d3,
                                         uint32_t a0, uint32_t a1, uint32_t a2, uint32_t a3,
                                         uint32_t b0, uint32_t b1) {
    asm volatile("mma.sync.aligned.m16n8k16.row.col.f32.bf16.bf16.f32 "
                 "{%0,%1,%2,%3},{%4,%5,%6,%7},{%8,%9},{%0,%1,%2,%3};"
                 : "+f"(d0), "+f"(d1), "+f"(d2), "+f"(d3)
                 : "r"(a0), "r"(a1), "r"(a2), "r"(a3), "r"(b0), "r"(b1));
}
__device__ __forceinline__ void ldsm_x4(uint32_t& r0, uint32_t& r1, uint32_t& r2, uint32_t& r3,
                                        uint32_t addr) {
    asm volatile("ldmatrix.sync.aligned.m8n8.x4.shared.b16 {%0,%1,%2,%3}, [%4];"
                 : "=r"(r0), "=r"(r1), "=r"(r2), "=r"(r3) : "r"(addr));
}
__device__ __forceinline__ void ldsm_x4t(uint32_t& r0, uint32_t& r1, uint32_t& r2, uint32_t& r3,
                                         uint32_t addr) {
    asm volatile("ldmatrix.sync.aligned.m8n8.x4.trans.shared.b16 {%0,%1,%2,%3}, [%4];"
                 : "=r"(r0), "=r"(r1), "=r"(r2), "=r"(r3) : "r"(addr));
}
__device__ __forceinline__ void cp_async16(uint32_t saddr, const void* gaddr, int srcsize) {
    asm volatile("cp.async.ca.shared.global [%0], [%1], 16, %2;"
                 :: "r"(saddr), "l"(gaddr), "r"(srcsize) : "memory");
}
__device__ __forceinline__ void cp_async16f(uint32_t saddr, const void* gaddr) {
    asm volatile("cp.async.ca.shared.global [%0], [%1], 16;"
                 :: "r"(saddr), "l"(gaddr) : "memory");
}
__device__ __forceinline__ void cp_commit() {
    asm volatile("cp.async.commit_group;" ::: "memory");
}
template<int N> __device__ __forceinline__ void cp_wait() {
    asm volatile("cp.async.wait_group %0;" :: "n"(N) : "memory");
}

// ---------------- 0) fused prep: bias gather + mask canon + weight round/permute ----------------
// blocks [0, NSEQ)              : bias row i = blockIdx.x
// blocks [NSEQ, NSEQ+40)        : mask canonicalization (40-block slice)
// blocks [NSEQ+40, NSEQ+40+256) : weight rounding (256 blocks x 256 threads)
#define WQ4 (768 * 256 / 4)
#define WP4 (256 * 256 / 4)
#define PREP_GRID (NSEQ + 40 + 256)

__global__ __launch_bounds__(256)
void prep_kernel(const unsigned char* __restrict__ mraw,
                 const int* __restrict__ rel_index,
                 const float* __restrict__ rpb, int num_rel,
                 const float* __restrict__ wq, const float* __restrict__ wp) {
    const int bid = blockIdx.x;
    if (bid < NSEQ) {
        // ---- bias gather, write-coalesced ----
        const int i = bid;
        const int* rrow = rel_index + (size_t)i * NSEQ;
        for (int p32 = threadIdx.x; p32 < NPAD / 2; p32 += 256) {
            int pos = p32 * 2;
            int base = pos & ~127;
            int rem  = pos & 127;
            int nt = (rem & 31) >> 1;
            int tt = rem >> 5;
            int j0 = base + nt * 8 + 2 * tt;
            bool in = (j0 + 1) < NSEQ;
            int r0 = 0, r1 = 0;
            if (in) { r0 = rrow[j0]; r1 = rrow[j0 + 1]; }
            #pragma unroll
            for (int h = 0; h < H_; h++) {
                uint32_t w = 0;
                if (in)
                    w = pack_bf16(rpb[h * num_rel + r0] * LOG2E,
                                  rpb[h * num_rel + r1] * LOG2E);
                *(uint32_t*)&g_bias[((size_t)h * NSEQ + i) * NPAD + pos] = w;
            }
        }
    } else if (bid < NSEQ + 40) {
        // ---- mask canonicalization (dtype auto-detect per block, deterministic) ----
        __shared__ int s_pos[4];
        if (threadIdx.x < 4) s_pos[threadIdx.x] = 0;
        __syncthreads();
        int loc[4] = {0, 0, 0, 0};
        for (int i = threadIdx.x; i < 4096; i += 256)
            if (mraw[i]) loc[i & 3] = 1;
        #pragma unroll
        for (int p = 0; p < 4; p++)
            if (loc[p]) atomicOr(&s_pos[p], 1);
        __syncthreads();
        int mode;                 // 0=uint8, 1=int32, 2=float32
        if (s_pos[1]) mode = 0;
        else if (s_pos[2] | s_pos[3]) mode = 2;
        else mode = 1;
        const int total = B_ * NPAD;
        const int slice = bid - NSEQ;
        for (int idx = slice * 256 + threadIdx.x; idx < total; idx += 40 * 256) {
            int b = idx / NPAD;
            int j = idx - b * NPAD;
            float v = -3e38f;
            if (j < NSEQ) {
                int i = b * NSEQ + j;
                bool mm;
                if (mode == 0)      mm = mraw[i] != 0;
                else if (mode == 1) mm = ((const int*)mraw)[i] != 0;
                else                mm = ((const float*)mraw)[i] != 0.f;
                v = mm ? -3e38f : 0.f;
            }
            int rem = j & 127;
            int nt = rem >> 3, tt = (rem >> 1) & 3, e = rem & 1;
            g_madd[b * NPAD + (j & ~127) + tt * 32 + nt * 2 + e] = v;
        }
    } else {
        // ---- weight tf32 round + k-permute ----
        int i = (bid - NSEQ - 40) * 256 + threadIdx.x;
        const float* src;
        float* dst;
        if (i < WQ4) { src = wq; dst = g_wq; }
        else if (i < WQ4 + WP4) { src = wp; dst = g_wp; i -= WQ4; }
        else return;
        float4 v = ((const float4*)src)[i];
        int base = i * 4;
        int row = base >> 8, kk = base & 255;
        int c32 = kk & ~31, rem = kk & 31;
        int ks = rem >> 3, h = (rem >> 2) & 1;
        float vals[4] = {tf32r(v.x), tf32r(v.y), tf32r(v.z), tf32r(v.w)};
        #pragma unroll
        for (int j = 0; j < 4; j++)
            dst[(size_t)row * 256 + c32 + j * 8 + ks * 2 + h] = vals[j];
    }
}

// ---------------- 2/4) tf32 GEMM, cp.async double-buffered, permuted-W B fragments ----------------
#define GP 36
#define G_STAGE 36864
#define GEMM_SMEM 73728

template<int MODE>
__global__ __launch_bounds__(256, 2)
void gemm_tf32(const float* __restrict__ A, const float* __restrict__ W,
               const float* __restrict__ bias, float* __restrict__ Cout, int Ntotal) {
    extern __shared__ float sm[];
    const uint32_t sbase = (uint32_t)__cvta_generic_to_shared(sm);
    const int tid  = threadIdx.x;
    const int warp = tid >> 5, lane = tid & 31;
    const int g = lane >> 2, t = lane & 3;
    const int wm = warp >> 1, wn = warp & 1;
    const int bm = blockIdx.x, bn = blockIdx.y;

    const float* Abase = A + (size_t)(bm * 128) * 256;
    const float* Wbase = W + (size_t)(bn * 128) * 256;

    auto stage = [&](int kc, int p) {
        #pragma unroll
        for (int it = 0; it < 4; it++) {
            int idx = tid + it * 256;
            int row = idx >> 3, ch = idx & 7;
            uint32_t sA = sbase + p * G_STAGE + row * (GP * 4) + ch * 16;
            cp_async16f(sA,         Abase + (size_t)row * 256 + kc * 32 + ch * 4);
            cp_async16f(sA + 18432, Wbase + (size_t)row * 256 + kc * 32 + ch * 4);
        }
        cp_commit();
    };

    float acc[2][8][4];
    #pragma unroll
    for (int i = 0; i < 2; i++)
        #pragma unroll
        for (int j = 0; j < 8; j++)
            #pragma unroll
            for (int k = 0; k < 4; k++) acc[i][j][k] = 0.f;

    stage(0, 0);
    for (int kc = 0; kc < 8; kc++) {
        int p = kc & 1;
        cp_wait<0>();
        __syncthreads();
        if (kc < 7) stage(kc + 1, p ^ 1);
        const float* As = sm + p * (G_STAGE / 4);
        const float* Bs = As + 18432 / 4;

        uint32_t aF[2][4][4];
        #pragma unroll
        for (int mt = 0; mt < 2; mt++) {
            int m0 = wm * 32 + mt * 16;
            #pragma unroll
            for (int ks = 0; ks < 4; ks++) {
                int k0 = ks * 8;
                if (MODE == 0) {
                    aF[mt][ks][0] = __float_as_uint(tf32r(As[(m0 + g    ) * GP + k0 + t    ]));
                    aF[mt][ks][1] = __float_as_uint(tf32r(As[(m0 + g + 8) * GP + k0 + t    ]));
                    aF[mt][ks][2] = __float_as_uint(tf32r(As[(m0 + g    ) * GP + k0 + t + 4]));
                    aF[mt][ks][3] = __float_as_uint(tf32r(As[(m0 + g + 8) * GP + k0 + t + 4]));
                } else {
                    aF[mt][ks][0] = __float_as_uint(As[(m0 + g    ) * GP + k0 + t    ]);
                    aF[mt][ks][1] = __float_as_uint(As[(m0 + g + 8) * GP + k0 + t    ]);
                    aF[mt][ks][2] = __float_as_uint(As[(m0 + g    ) * GP + k0 + t + 4]);
                    aF[mt][ks][3] = __float_as_uint(As[(m0 + g + 8) * GP + k0 + t + 4]);
                }
            }
        }
        #pragma unroll
        for (int np = 0; np < 4; np++) {
            uint4 bv[2][2];
            #pragma unroll
            for (int e = 0; e < 2; e++) {
                int n0 = wn * 64 + (np * 2 + e) * 8;
                const float4* bp = (const float4*)&Bs[(n0 + g) * GP + 8 * t];
                bv[e][0] = *(const uint4*)&bp[0];
                bv[e][1] = *(const uint4*)&bp[1];
            }
            #pragma unroll
            for (int ks = 0; ks < 4; ks++) {
                #pragma unroll
                for (int e = 0; e < 2; e++) {
                    int nt = np * 2 + e;
                    uint32_t b0 = u4w(bv[e][ks >> 1], (ks & 1) * 2);
                    uint32_t b1 = u4w(bv[e][ks >> 1], (ks & 1) * 2 + 1);
                    mma_tf32(acc[0][nt][0], acc[0][nt][1], acc[0][nt][2], acc[0][nt][3],
                             aF[0][ks][0], aF[0][ks][1], aF[0][ks][2], aF[0][ks][3], b0, b1);
                    mma_tf32(acc[1][nt][0], acc[1][nt][1], acc[1][nt][2], acc[1][nt][3],
                             aF[1][ks][0], aF[1][ks][1], aF[1][ks][2], aF[1][ks][3], b0, b1);
                }
            }
        }
        __syncthreads();
    }

    if (MODE == 0) {
        const int which = bn >> 1;
        __nv_bfloat16* dst = (which == 0) ? g_q : (which == 1) ? g_k : g_v;
        const float sc = (which == 0) ? QK_SCALE : 1.f;
        #pragma unroll
        for (int mt = 0; mt < 2; mt++) {
            int r0 = bm * 128 + wm * 32 + mt * 16 + g;
            int r8 = r0 + 8;
            int b0i = r0 / NSEQ, n0 = r0 - b0i * NSEQ;
            int b8i = r8 / NSEQ, n8 = r8 - b8i * NSEQ;
            #pragma unroll
            for (int nt = 0; nt < 8; nt++) {
                int c0 = bn * 128 + wn * 64 + nt * 8 + 2 * t;
                int h = (c0 >> 5) & 7, d = c0 & 31;
                uint32_t lo = pack_bf16(acc[mt][nt][0] * sc, acc[mt][nt][1] * sc);
                uint32_t hi = pack_bf16(acc[mt][nt][2] * sc, acc[mt][nt][3] * sc);
                *(uint32_t*)&dst[((size_t)(b0i * 8 + h) * NSEQ + n0) * 32 + d] = lo;
                *(uint32_t*)&dst[((size_t)(b8i * 8 + h) * NSEQ + n8) * 32 + d] = hi;
            }
        }
    } else {
        #pragma unroll
        for (int mt = 0; mt < 2; mt++) {
            int r0 = bm * 128 + wm * 32 + mt * 16 + g;
            #pragma unroll
            for (int nt = 0; nt < 8; nt++) {
                int c0 = bn * 128 + wn * 64 + nt * 8 + 2 * t;
                float bb0 = bias[c0], bb1 = bias[c0 + 1];
                float2 v0 = make_float2(acc[mt][nt][0] + bb0, acc[mt][nt][1] + bb1);
                float2 v1 = make_float2(acc[mt][nt][2] + bb0, acc[mt][nt][3] + bb1);
                *(float2*)&Cout[(size_t)r0       * Ntotal + c0] = v0;
                *(float2*)&Cout[(size_t)(r0 + 8) * Ntotal + c0] = v1;
            }
        }
    }
}

// ---------------- 3) flash attention (round-12 config): 4 warps x 32 Q-rows ----------------
#define KV_PITCH 80
#define SM_STAGE 20480
#define ATTN_SMEM 40960

__global__ void __launch_bounds__(128, 3) attn_kernel() {
    extern __shared__ char smx[];
    const uint32_t sbase = (uint32_t)__cvta_generic_to_shared(smx);

    const int tid  = threadIdx.x;
    const int warp = tid >> 5, lane = tid & 31;
    const int g = lane >> 2, t = lane & 3;
    const int qt = blockIdx.x, bh = blockIdx.y;
    const int b = bh >> 3, h = bh & 7;
    const int qbase = qt * 128;

    int r[4], rc[4];
    #pragma unroll
    for (int i = 0; i < 4; i++) {
        r[i]  = qbase + warp * 32 + g + i * 8;
        rc[i] = min(r[i], NSEQ - 1);
    }

    const __nv_bfloat16* kbase = g_k + (size_t)bh * NSEQ * 32;
    const __nv_bfloat16* vbase = g_v + (size_t)bh * NSEQ * 32;

    uint32_t aq[2][2][4];
    #pragma unroll
    for (int sub = 0; sub < 2; sub++) {
        const __nv_bfloat16* qlo = g_q + ((size_t)bh * NSEQ + rc[2 * sub])     * 32;
        const __nv_bfloat16* qhi = g_q + ((size_t)bh * NSEQ + rc[2 * sub + 1]) * 32;
        #pragma unroll
        for (int kk = 0; kk < 2; kk++) {
            aq[sub][kk][0] = *(const uint32_t*)(qlo + kk * 16 + 2 * t);
            aq[sub][kk][1] = *(const uint32_t*)(qhi + kk * 16 + 2 * t);
            aq[sub][kk][2] = *(const uint32_t*)(qlo + kk * 16 + 2 * t + 8);
            aq[sub][kk][3] = *(const uint32_t*)(qhi + kk * 16 + 2 * t + 8);
        }
    }

    const __nv_bfloat16* bptr[4];
    #pragma unroll
    for (int i = 0; i < 4; i++)
        bptr[i] = g_bias + ((size_t)h * NSEQ + rc[i]) * NPAD + t * 32;
    const float* mptr = g_madd + b * NPAD + t * 32;

    const uint32_t lk_row = (lane & 7);
    const uint32_t lk_grp = (lane >> 3);
    const uint32_t offK = lk_row * KV_PITCH + lk_grp * 16;
    const uint32_t offV = ((lk_grp & 1) * 8 + lk_row) * KV_PITCH + (lk_grp >> 1) * 16 + 10240;

    float accO[2][4][4];
    #pragma unroll
    for (int s = 0; s < 2; s++)
        #pragma unroll
        for (int i = 0; i < 4; i++)
            #pragma unroll
            for (int j = 0; j < 4; j++) accO[s][i][j] = 0.f;
    float l[4] = {0.f, 0.f, 0.f, 0.f};

    auto stage = [&](int kt, int p) {
        const int kb = kt * 128;
        #pragma unroll
        for (int it = 0; it < 4; it++) {
            int idx = tid + it * 128;
            int row = idx >> 2, ch = idx & 3;
            int key = kb + row;
            int sz = (key < NSEQ) ? 16 : 0;
            uint32_t s0 = sbase + p * SM_STAGE + row * KV_PITCH + ch * 16;
            cp_async16(s0,         kbase + (size_t)key * 32 + ch * 8, sz);
            cp_async16(s0 + 10240, vbase + (size_t)key * 32 + ch * 8, sz);
        }
        cp_commit();
    };

    stage(0, 0);

    for (int kt = 0; kt < 10; kt++) {
        const int p  = kt & 1;
        const int kb = kt * 128;
        cp_wait<0>();
        __syncthreads();
        if (kt < 9) stage(kt + 1, p ^ 1);

        const uint32_t addrK = sbase + p * SM_STAGE + offK;
        const uint32_t addrV = sbase + p * SM_STAGE + offV;

        #pragma unroll
        for (int half = 0; half < 2; half++) {
            float S[2][8][4];
            #pragma unroll
            for (int qq = 0; qq < 2; qq++) {
                uint4 bu[4];
                #pragma unroll
                for (int i = 0; i < 4; i++)
                    bu[i] = *(const uint4*)(bptr[i] + kb + half * 16 + qq * 8);
                float4 m0 = *(const float4*)(mptr + kb + half * 16 + qq * 8);
                float4 m1 = *(const float4*)(mptr + kb + half * 16 + qq * 8 + 4);
                #pragma unroll
                for (int w = 0; w < 4; w++) {
                    int ntl = qq * 4 + w;
                    float mx = (w == 0) ? m0.x : (w == 1) ? m0.z : (w == 2) ? m1.x : m1.z;
                    float my = (w == 0) ? m0.y : (w == 1) ? m0.w : (w == 2) ? m1.y : m1.w;
                    #pragma unroll
                    for (int sub = 0; sub < 2; sub++) {
                        float2 bl  = unpack_bf16(u4w(bu[2 * sub],     w));
                        float2 bh2 = unpack_bf16(u4w(bu[2 * sub + 1], w));
                        S[sub][ntl][0] = bl.x + mx;   S[sub][ntl][1] = bl.y + my;
                        S[sub][ntl][2] = bh2.x + mx;  S[sub][ntl][3] = bh2.y + my;
                    }
                }
            }
            #pragma unroll
            for (int ntl = 0; ntl < 8; ntl++) {
                uint32_t b0, b1, b2, b3;
                ldsm_x4(b0, b1, b2, b3, addrK + (half * 8 + ntl) * (8 * KV_PITCH));
                #pragma unroll
                for (int sub = 0; sub < 2; sub++) {
                    mma_bf16(S[sub][ntl][0], S[sub][ntl][1], S[sub][ntl][2], S[sub][ntl][3],
                             aq[sub][0][0], aq[sub][0][1], aq[sub][0][2], aq[sub][0][3], b0, b1);
                    mma_bf16(S[sub][ntl][0], S[sub][ntl][1], S[sub][ntl][2], S[sub][ntl][3],
                             aq[sub][1][0], aq[sub][1][1], aq[sub][1][2], aq[sub][1][3], b2, b3);
                }
            }
            #pragma unroll
            for (int ntl = 0; ntl < 8; ntl++) {
                #pragma unroll
                for (int sub = 0; sub < 2; sub++) {
                    S[sub][ntl][0] = ex2f(S[sub][ntl][0]);
                    S[sub][ntl][1] = ex2f(S[sub][ntl][1]);
                    S[sub][ntl][2] = ex2f(S[sub][ntl][2]);
                    S[sub][ntl][3] = ex2f(S[sub][ntl][3]);
                    l[2 * sub]     += S[sub][ntl][0] + S[sub][ntl][1];
                    l[2 * sub + 1] += S[sub][ntl][2] + S[sub][ntl][3];
                }
            }
            #pragma unroll
            for (int jl = 0; jl < 4; jl++) {
                uint32_t a[2][4];
                #pragma unroll
                for (int sub = 0; sub < 2; sub++) {
                    a[sub][0] = pack_bf16(S[sub][2 * jl][0],     S[sub][2 * jl][1]);
                    a[sub][1] = pack_bf16(S[sub][2 * jl][2],     S[sub][2 * jl][3]);
                    a[sub][2] = pack_bf16(S[sub][2 * jl + 1][0], S[sub][2 * jl + 1][1]);
                    a[sub][3] = pack_bf16(S[sub][2 * jl + 1][2], S[sub][2 * jl + 1][3]);
                }
                #pragma unroll
                for (int nob = 0; nob < 4; nob += 2) {
                    uint32_t v0, v1, v2, v3;
                    ldsm_x4t(v0, v1, v2, v3,
                             addrV + (half * 4 + jl) * (16 * KV_PITCH) + nob * 16);
                    #pragma unroll
                    for (int sub = 0; sub < 2; sub++) {
                        mma_bf16(accO[sub][nob][0], accO[sub][nob][1],
                                 accO[sub][nob][2], accO[sub][nob][3],
                                 a[sub][0], a[sub][1], a[sub][2], a[sub][3], v0, v1);
                        mma_bf16(accO[sub][nob + 1][0], accO[sub][nob + 1][1],
                                 accO[sub][nob + 1][2], accO[sub][nob + 1][3],
                                 a[sub][0], a[sub][1], a[sub][2], a[sub][3], v2, v3);
                    }
                }
            }
        }
    }

    #pragma unroll
    for (int i = 0; i < 4; i++) {
        l[i] += __shfl_xor_sync(0xffffffffu, l[i], 1);
        l[i] += __shfl_xor_sync(0xffffffffu, l[i], 2);
    }

    // outputs tf32-rounded: proj GEMM consumes g_att without further rounding
    #pragma unroll
    for (int sub = 0; sub < 2; sub++) {
        float il = 1.f / l[2 * sub];
        float ih = 1.f / l[2 * sub + 1];
        if (r[2 * sub] < NSEQ) {
            #pragma unroll
            for (int no = 0; no < 4; no++) {
                float2 v = make_float2(tf32r(accO[sub][no][0] * il), tf32r(accO[sub][no][1] * il));
                *(float2*)&g_att[((size_t)b * NSEQ + r[2 * sub]) * 256 + h * 32 + no * 8 + 2 * t] = v;
            }
        }
        if (r[2 * sub + 1] < NSEQ) {
            #pragma unroll
            for (int no = 0; no < 4; no++) {
                float2 v = make_float2(tf32r(accO[sub][no][2] * ih), tf32r(accO[sub][no][3] * ih));
                *(float2*)&g_att[((size_t)b * NSEQ + r[2 * sub + 1]) * 256 + h * 32 + no * 8 + 2 * t] = v;
            }
        }
    }
}

// ---------------- launch ----------------
extern "C" void kernel_launch(void* const* d_in, const int* in_sizes, int n_in,
                              void* d_out, int out_size) {
    const float*         x       = (const float*)d_in[0];
    const unsigned char* mask    = (const unsigned char*)d_in[1];
    const float*         w_qkv   = (const float*)d_in[2];
    const float*         w_proj  = (const float*)d_in[3];
    const float*         b_proj  = (const float*)d_in[4];
    const float*         rpb     = (const float*)d_in[5];
    const int*           relidx  = (const int*)d_in[6];
    const int num_rel = in_sizes[5] / H_;

    cudaFuncSetAttribute(gemm_tf32<0>, cudaFuncAttributeMaxDynamicSharedMemorySize, GEMM_SMEM);
    cudaFuncSetAttribute(gemm_tf32<1>, cudaFuncAttributeMaxDynamicSharedMemorySize, GEMM_SMEM);
    cudaFuncSetAttribute(attn_kernel,  cudaFuncAttributeMaxDynamicSharedMemorySize, ATTN_SMEM);

    void *p_att = nullptr, *p_wq = nullptr, *p_wp = nullptr;
    cudaGetSymbolAddress(&p_att, g_att);
    cudaGetSymbolAddress(&p_wq,  g_wq);
    cudaGetSymbolAddress(&p_wp,  g_wp);

    prep_kernel<<<PREP_GRID, 256>>>(mask, relidx, rpb, num_rel, w_qkv, w_proj);
    gemm_tf32<0><<<dim3(MROWS / 128, 768 / 128), 256, GEMM_SMEM>>>(
        x, (const float*)p_wq, nullptr, nullptr, 768);
    attn_kernel<<<dim3(10, B_ * H_), 128, ATTN_SMEM>>>();
    gemm_tf32<1><<<dim3(MROWS / 128, 256 / 128), 256, GEMM_SMEM>>>(
        (const float*)p_att, (const float*)p_wp, b_proj, (float*)d_out, 256);
}